// round 15
// baseline (speedup 1.0000x reference)
#include <cuda_runtime.h>
#include <cuda_bf16.h>
#include <cstdint>

#define NNODES 100000
#define NEDGES 1600000
#define DIM 128
#define NGRAPHS 128
#define NLAYERS 3
#define BN_EPS 1e-5f
#define NCHUNK ((NNODES + 1023) / 1024)
#define NTILES ((NNODES + 127) / 128)
#define NSMS 148

// ---------------- scratch (static device globals; no allocation) -------------
__device__ float g_aggr[(size_t)NNODES * DIM];
__device__ float g_h[(size_t)NNODES * DIM];
__device__ float g_sum[DIM];
__device__ float g_sumsq[DIM];

__device__ __align__(16) __nv_bfloat16 g_bs_hi[6 * DIM * DIM];
__device__ __align__(16) __nv_bfloat16 g_bs_lo[6 * DIM * DIM];

__device__ int g_cnt[NNODES];
__device__ int g_rowptr[NNODES + 1];
__device__ int g_cur[NNODES];
__device__ int g_srcbuf[NEDGES];
__device__ int g_csum[NCHUNK];
__device__ int g_coff[NCHUNK];

// ---------------- CSR construction -------------------------------------------
__global__ void k_zero_cnt(float* __restrict__ gcat) {
    int i = blockIdx.x * blockDim.x + threadIdx.x;
    int stride = gridDim.x * blockDim.x;
    for (int j = i; j < NNODES; j += stride) g_cnt[j] = 0;
    for (int j = i; j < NGRAPHS * NLAYERS * DIM; j += stride) gcat[j] = 0.f;
    if (blockIdx.x == 0 && threadIdx.x < DIM) {
        g_sum[threadIdx.x] = 0.f;
        g_sumsq[threadIdx.x] = 0.f;
    }
}

__global__ void k_hist(const int* __restrict__ ei) {
    int i = blockIdx.x * blockDim.x + threadIdx.x;
    if (i < NEDGES / 4) {
        int4 d = ((const int4*)(ei + NEDGES))[i];
        atomicAdd(&g_cnt[d.x], 1);
        atomicAdd(&g_cnt[d.y], 1);
        atomicAdd(&g_cnt[d.z], 1);
        atomicAdd(&g_cnt[d.w], 1);
    }
}

__global__ void k_chunksum() {
    __shared__ int wsum[32];
    int i = blockIdx.x * 1024 + threadIdx.x;
    int v = (i < NNODES) ? g_cnt[i] : 0;
    #pragma unroll
    for (int o = 16; o > 0; o >>= 1) v += __shfl_down_sync(~0u, v, o);
    if ((threadIdx.x & 31) == 0) wsum[threadIdx.x >> 5] = v;
    __syncthreads();
    if (threadIdx.x < 32) {
        int s = wsum[threadIdx.x];
        #pragma unroll
        for (int o = 16; o > 0; o >>= 1) s += __shfl_down_sync(~0u, s, o);
        if (threadIdx.x == 0) g_csum[blockIdx.x] = s;
    }
}

__global__ void k_scanchunks() {
    __shared__ int sh[4];
    const int tid = threadIdx.x;
    const int lane = tid & 31;
    const int wid = tid >> 5;
    int v = (tid < NCHUNK) ? g_csum[tid] : 0;
    int x = v;
    #pragma unroll
    for (int o = 1; o < 32; o <<= 1) {
        int t = __shfl_up_sync(~0u, x, o);
        if (lane >= o) x += t;
    }
    if (lane == 31) sh[wid] = x;
    __syncthreads();
    int base = 0;
    #pragma unroll
    for (int w = 0; w < 4; w++) if (w < wid) base += sh[w];
    int excl = base + x - v;
    if (tid < NCHUNK) g_coff[tid] = excl;
    if (tid == 127) g_rowptr[NNODES] = base + x;
}

__global__ void k_scanwrite() {
    __shared__ int wsum[32];
    const int tid = threadIdx.x;
    const int lane = tid & 31;
    const int wid = tid >> 5;
    int i = blockIdx.x * 1024 + tid;
    int v = (i < NNODES) ? g_cnt[i] : 0;
    int x = v;
    #pragma unroll
    for (int o = 1; o < 32; o <<= 1) {
        int t = __shfl_up_sync(~0u, x, o);
        if (lane >= o) x += t;
    }
    if (lane == 31) wsum[wid] = x;
    __syncthreads();
    if (wid == 0) {
        int s = wsum[lane];
        #pragma unroll
        for (int o = 1; o < 32; o <<= 1) {
            int t = __shfl_up_sync(~0u, s, o);
            if (lane >= o) s += t;
        }
        wsum[lane] = s;
    }
    __syncthreads();
    int excl = g_coff[blockIdx.x] + x - v + (wid > 0 ? wsum[wid - 1] : 0);
    if (i < NNODES) { g_rowptr[i] = excl; g_cur[i] = excl; }
}

__global__ void k_fill(const int* __restrict__ ei) {
    int i = blockIdx.x * blockDim.x + threadIdx.x;
    if (i < NEDGES / 4) {
        int4 s = ((const int4*)ei)[i];
        int4 d = ((const int4*)(ei + NEDGES))[i];
        int p0 = atomicAdd(&g_cur[d.x], 1); g_srcbuf[p0] = s.x;
        int p1 = atomicAdd(&g_cur[d.y], 1); g_srcbuf[p1] = s.y;
        int p2 = atomicAdd(&g_cur[d.z], 1); g_srcbuf[p2] = s.z;
        int p3 = atomicAdd(&g_cur[d.w], 1); g_srcbuf[p3] = s.w;
    }
}

// ---------------- W^T -> bf16 hi/lo Bs[n][k] (coalesced reads) -----------------
__global__ void k_wconv(const float* __restrict__ W1, const float* __restrict__ W2) {
    int which = blockIdx.x;
    int layer = which >> 1;
    const float* W = (which & 1) ? (W2 + (size_t)layer * DIM * DIM)
                                 : (W1 + (size_t)layer * DIM * DIM);
    __nv_bfloat16* hi = g_bs_hi + (size_t)which * DIM * DIM;
    __nv_bfloat16* lo = g_bs_lo + (size_t)which * DIM * DIM;
    for (int e = threadIdx.x; e < DIM * DIM; e += blockDim.x) {
        int k = e >> 7, n = e & 127;       // consecutive threads -> consecutive n
        float x = W[e];                     // coalesced read W[k][n]
        __nv_bfloat16 h = __float2bfloat16(x);
        __nv_bfloat16 l = __float2bfloat16(x - __bfloat162float(h));
        hi[n * DIM + k] = h;               // Bs[n][k] = W[k][n]
        lo[n * DIM + k] = l;
    }
}

// ---------------- gather aggregation (R11 exact) -------------------------------
__global__ void k_aggregate(const float* __restrict__ zin, int pin) {
    if (blockIdx.x == 0 && threadIdx.x < DIM) {
        g_sum[threadIdx.x] = 0.f;
        g_sumsq[threadIdx.x] = 0.f;
    }
    const int lane = threadIdx.x & 31;
    const int w = (blockIdx.x * blockDim.x + threadIdx.x) >> 5;
    if (w >= NNODES) return;
    const int c = lane * 4;
    const int beg = g_rowptr[w];
    const int end = g_rowptr[w + 1];
    float4 a0 = *(const float4*)(zin + (size_t)w * pin + c);
    float4 a1 = make_float4(0.f, 0.f, 0.f, 0.f);
    float4 a2 = a1, a3 = a1;
    int e = beg;
    for (; e + 4 <= end; e += 4) {
        int s0 = __ldg(g_srcbuf + e), s1 = __ldg(g_srcbuf + e + 1);
        int s2 = __ldg(g_srcbuf + e + 2), s3 = __ldg(g_srcbuf + e + 3);
        float4 v0 = *(const float4*)(zin + (size_t)s0 * pin + c);
        float4 v1 = *(const float4*)(zin + (size_t)s1 * pin + c);
        float4 v2 = *(const float4*)(zin + (size_t)s2 * pin + c);
        float4 v3 = *(const float4*)(zin + (size_t)s3 * pin + c);
        a0.x += v0.x; a0.y += v0.y; a0.z += v0.z; a0.w += v0.w;
        a1.x += v1.x; a1.y += v1.y; a1.z += v1.z; a1.w += v1.w;
        a2.x += v2.x; a2.y += v2.y; a2.z += v2.z; a2.w += v2.w;
        a3.x += v3.x; a3.y += v3.y; a3.z += v3.z; a3.w += v3.w;
    }
    for (; e < end; e++) {
        int s = __ldg(g_srcbuf + e);
        float4 v = *(const float4*)(zin + (size_t)s * pin + c);
        a0.x += v.x; a0.y += v.y; a0.z += v.z; a0.w += v.w;
    }
    a0.x += a1.x + a2.x + a3.x;
    a0.y += a1.y + a2.y + a3.y;
    a0.z += a1.z + a2.z + a3.z;
    a0.w += a1.w + a2.w + a3.w;
    *(float4*)(g_aggr + (size_t)w * DIM + c) = a0;
}

// ---------------- persistent fused 2-GEMM MLP + BN stats (R11 exact) ----------
#define PITCHB 272
#define SM_AHI 0
#define SM_ALO (SM_AHI + 128 * PITCHB)
#define SM_B1HI (SM_ALO + 128 * PITCHB)
#define SM_B1LO (SM_B1HI + 128 * PITCHB)
#define SM_B2HI (SM_B1LO + 128 * PITCHB)
#define SM_B2LO (SM_B2HI + 128 * PITCHB)
#define SM_SUM (SM_B2LO + 128 * PITCHB)       // float [8][128]
#define SM_SQ  (SM_SUM + 8 * 128 * 4)
#define SM_BS1 (SM_SQ + 8 * 128 * 4)
#define SM_BS2 (SM_BS1 + 512)
#define SMEM_TOT (SM_BS2 + 512)

#define MMA16816(c, a0, a1, a2, a3, b0, b1) \
    asm volatile("mma.sync.aligned.m16n8k16.row.col.f32.bf16.bf16.f32 " \
        "{%0,%1,%2,%3}, {%4,%5,%6,%7}, {%8,%9}, {%0,%1,%2,%3};" \
        : "+f"((c)[0]), "+f"((c)[1]), "+f"((c)[2]), "+f"((c)[3]) \
        : "r"(a0), "r"(a1), "r"(a2), "r"(a3), "r"(b0), "r"(b1))

__device__ __forceinline__ uint32_t pack_hi2(float x0, float x1, uint32_t& lo) {
    __nv_bfloat16 h0 = __float2bfloat16(x0);
    __nv_bfloat16 h1 = __float2bfloat16(x1);
    __nv_bfloat16 l0 = __float2bfloat16(x0 - __bfloat162float(h0));
    __nv_bfloat16 l1 = __float2bfloat16(x1 - __bfloat162float(h1));
    lo = (uint32_t)__bfloat16_as_ushort(l0) | ((uint32_t)__bfloat16_as_ushort(l1) << 16);
    return (uint32_t)__bfloat16_as_ushort(h0) | ((uint32_t)__bfloat16_as_ushort(h1) << 16);
}

__device__ __forceinline__ void mma_3pass(char* smem, int bhi_off, int blo_off,
                                          int m0, int n0, int g, int t,
                                          float c[2][8][4]) {
    #pragma unroll
    for (int mt = 0; mt < 2; mt++)
        #pragma unroll
        for (int nt = 0; nt < 8; nt++)
            #pragma unroll
            for (int q = 0; q < 4; q++) c[mt][nt][q] = 0.f;
    #pragma unroll
    for (int p = 0; p < 3; p++) {
        const char* As = smem + (p == 2 ? SM_ALO : SM_AHI);
        const char* Bs = smem + (p == 1 ? blo_off : bhi_off);
        #pragma unroll
        for (int ks = 0; ks < 8; ks++) {
            const int kb = ks * 16;
            uint32_t a[2][4];
            #pragma unroll
            for (int mt = 0; mt < 2; mt++) {
                const char* pr = As + (m0 + mt * 16 + g) * PITCHB + (kb + 2 * t) * 2;
                a[mt][0] = *(const uint32_t*)pr;
                a[mt][1] = *(const uint32_t*)(pr + 8 * PITCHB);
                a[mt][2] = *(const uint32_t*)(pr + 16);
                a[mt][3] = *(const uint32_t*)(pr + 8 * PITCHB + 16);
            }
            #pragma unroll
            for (int nt = 0; nt < 8; nt++) {
                const char* pb = Bs + (n0 + nt * 8 + g) * PITCHB + (kb + 2 * t) * 2;
                uint32_t b0 = *(const uint32_t*)pb;
                uint32_t b1 = *(const uint32_t*)(pb + 16);
                MMA16816(c[0][nt], a[0][0], a[0][1], a[0][2], a[0][3], b0, b1);
                MMA16816(c[1][nt], a[1][0], a[1][1], a[1][2], a[1][3], b0, b1);
            }
        }
    }
}

__global__ void __launch_bounds__(256, 1)
k_mlp(const float* __restrict__ Afp,
      const __nv_bfloat16* __restrict__ B1hi, const __nv_bfloat16* __restrict__ B1lo,
      const __nv_bfloat16* __restrict__ B2hi, const __nv_bfloat16* __restrict__ B2lo,
      const float* __restrict__ bias1, const float* __restrict__ bias2,
      float* __restrict__ outh, int nrows) {
    extern __shared__ char smem[];
    const int tid = threadIdx.x;
    const int wid = tid >> 5;
    const int lane = tid & 31;
    const int g = lane >> 2;
    const int t = lane & 3;

    // one-time setup
    {
        float* z = (float*)(smem + SM_SUM);
        #pragma unroll
        for (int i = 0; i < 8; i++) z[tid + i * 256] = 0.f;
        if (tid < DIM) {
            ((float*)(smem + SM_BS1))[tid] = bias1[tid];
            ((float*)(smem + SM_BS2))[tid] = bias2[tid];
        }
        const uint4* s1h = (const uint4*)B1hi;
        const uint4* s1l = (const uint4*)B1lo;
        const uint4* s2h = (const uint4*)B2hi;
        const uint4* s2l = (const uint4*)B2lo;
        #pragma unroll
        for (int i = 0; i < 8; i++) {
            int idx = tid + i * 256;
            int r = idx >> 4, k = (idx & 15) * 8;
            int off = r * PITCHB + k * 2;
            *(uint4*)(smem + SM_B1HI + off) = s1h[idx];
            *(uint4*)(smem + SM_B1LO + off) = s1l[idx];
            *(uint4*)(smem + SM_B2HI + off) = s2h[idx];
            *(uint4*)(smem + SM_B2LO + off) = s2l[idx];
        }
    }

    const int m0 = (wid >> 1) * 32;
    const int n0 = (wid & 1) * 64;
    float c[2][8][4];

    for (int tile = blockIdx.x; tile < NTILES; tile += gridDim.x) {
        const int row0 = tile * 128;

        // load + split A (fp32 -> bf16 hi/lo planes)
        #pragma unroll
        for (int i = 0; i < 16; i++) {
            int idx = tid + i * 256;
            int r = idx >> 5, k = (idx & 31) * 4;
            int gr = row0 + r;
            float4 v = make_float4(0.f, 0.f, 0.f, 0.f);
            if (gr < nrows) v = *(const float4*)(Afp + (size_t)gr * DIM + k);
            uint32_t l0, l1, h0, h1;
            h0 = pack_hi2(v.x, v.y, l0);
            h1 = pack_hi2(v.z, v.w, l1);
            *(uint2*)(smem + SM_AHI + r * PITCHB + k * 2) = make_uint2(h0, h1);
            *(uint2*)(smem + SM_ALO + r * PITCHB + k * 2) = make_uint2(l0, l1);
        }
        __syncthreads();

        // ---- GEMM1 ----
        mma_3pass(smem, SM_B1HI, SM_B1LO, m0, n0, g, t, c);
        __syncthreads();

        // epilogue1: bias1+relu -> hi/lo back into A planes
        #pragma unroll
        for (int nt = 0; nt < 8; nt++) {
            const int ce = n0 + nt * 8 + 2 * t;
            const float be = ((const float*)(smem + SM_BS1))[ce];
            const float bo = ((const float*)(smem + SM_BS1))[ce + 1];
            #pragma unroll
            for (int mt = 0; mt < 2; mt++) {
                #pragma unroll
                for (int rr = 0; rr < 2; rr++) {
                    const int r = m0 + mt * 16 + g + rr * 8;
                    float ve = fmaxf(c[mt][nt][rr * 2] + be, 0.f);
                    float vo = fmaxf(c[mt][nt][rr * 2 + 1] + bo, 0.f);
                    uint32_t lo;
                    uint32_t hi = pack_hi2(ve, vo, lo);
                    *(uint32_t*)(smem + SM_AHI + r * PITCHB + ce * 2) = hi;
                    *(uint32_t*)(smem + SM_ALO + r * PITCHB + ce * 2) = lo;
                }
            }
        }
        __syncthreads();

        // ---- GEMM2 ----
        mma_3pass(smem, SM_B2HI, SM_B2LO, m0, n0, g, t, c);

        // epilogue2: bias2+relu -> fp32 out + stats
        #pragma unroll
        for (int nt = 0; nt < 8; nt++) {
            const int ce = n0 + nt * 8 + 2 * t;
            const float be = ((const float*)(smem + SM_BS2))[ce];
            const float bo = ((const float*)(smem + SM_BS2))[ce + 1];
            float se = 0.f, so = 0.f, qe = 0.f, qo = 0.f;
            #pragma unroll
            for (int mt = 0; mt < 2; mt++) {
                #pragma unroll
                for (int rr = 0; rr < 2; rr++) {
                    const int gr = row0 + m0 + mt * 16 + g + rr * 8;
                    float ve = fmaxf(c[mt][nt][rr * 2] + be, 0.f);
                    float vo = fmaxf(c[mt][nt][rr * 2 + 1] + bo, 0.f);
                    if (gr >= nrows) { ve = 0.f; vo = 0.f; }
                    se += ve; so += vo;
                    qe += ve * ve; qo += vo * vo;
                    if (gr < nrows)
                        *(float2*)(outh + (size_t)gr * DIM + ce) = make_float2(ve, vo);
                }
            }
            #pragma unroll
            for (int o = 4; o < 32; o <<= 1) {
                se += __shfl_xor_sync(~0u, se, o);
                so += __shfl_xor_sync(~0u, so, o);
                qe += __shfl_xor_sync(~0u, qe, o);
                qo += __shfl_xor_sync(~0u, qo, o);
            }
            if (g == 0) {
                float* ps = (float*)(smem + SM_SUM) + wid * 128;
                float* pq = (float*)(smem + SM_SQ) + wid * 128;
                ps[ce] = se; ps[ce + 1] = so;
                pq[ce] = qe; pq[ce + 1] = qo;
            }
        }
        __syncthreads();

        if (tid < 128) {
            const float* ps = (const float*)(smem + SM_SUM);
            float s = 0.f;
            #pragma unroll
            for (int w = 0; w < 8; w++) s += ps[w * 128 + tid];
            atomicAdd(&g_sum[tid], s);
        } else {
            const float* pq = (const float*)(smem + SM_SQ);
            const int f = tid - 128;
            float s = 0.f;
            #pragma unroll
            for (int w = 0; w < 8; w++) s += pq[w * 128 + f];
            atomicAdd(&g_sumsq[f], s);
        }
        __syncthreads();
    }
}

// ---------------- normalize + z_cat slice + graph add-pool (R11 exact) --------
#define NP_CH 128
__global__ void k_norm_pool(const float* __restrict__ h,
                            const int* __restrict__ batch,
                            const float* __restrict__ gamma,
                            const float* __restrict__ beta,
                            float* __restrict__ zout,
                            float* __restrict__ gout) {
    __shared__ float s_sc[DIM], s_sh[DIM];
    if (threadIdx.x < DIM) {
        int f = threadIdx.x;
        float mean = g_sum[f] * (1.0f / NNODES);
        float var = g_sumsq[f] * (1.0f / NNODES) - mean * mean;
        float inv = rsqrtf(var + BN_EPS);
        float sc = gamma[f] * inv;
        s_sc[f] = sc;
        s_sh[f] = beta[f] - mean * sc;
    }
    __syncthreads();

    const int f4 = (threadIdx.x & 31) * 4;
    const int ln = threadIdx.x >> 5;
    const int r0 = blockIdx.x * NP_CH;
    const int rend = min(r0 + NP_CH, NNODES);
    const float4 sc = *(const float4*)(s_sc + f4);
    const float4 sh = *(const float4*)(s_sh + f4);
    float4 acc = make_float4(0.f, 0.f, 0.f, 0.f);
    int cur = -1;
    for (int r = r0 + ln; r < rend; r += 8) {
        float4 x = *(const float4*)(h + (size_t)r * DIM + f4);
        float4 v;
        v.x = fmaf(x.x, sc.x, sh.x);
        v.y = fmaf(x.y, sc.y, sh.y);
        v.z = fmaf(x.z, sc.z, sh.z);
        v.w = fmaf(x.w, sc.w, sh.w);
        *(float4*)(zout + (size_t)r * (NLAYERS * DIM) + f4) = v;
        int b = batch[r];
        if (b != cur) {
            if (cur >= 0) {
                float* p = gout + (size_t)cur * (NLAYERS * DIM) + f4;
                atomicAdd(p, acc.x); atomicAdd(p + 1, acc.y);
                atomicAdd(p + 2, acc.z); atomicAdd(p + 3, acc.w);
            }
            cur = b;
            acc = v;
        } else {
            acc.x += v.x; acc.y += v.y; acc.z += v.z; acc.w += v.w;
        }
    }
    if (cur >= 0) {
        float* p = gout + (size_t)cur * (NLAYERS * DIM) + f4;
        atomicAdd(p, acc.x); atomicAdd(p + 1, acc.y);
        atomicAdd(p + 2, acc.z); atomicAdd(p + 3, acc.w);
    }
}

// ---------------- launch -------------------------------------------------------
extern "C" void kernel_launch(void* const* d_in, const int* in_sizes, int n_in,
                              void* d_out, int out_size) {
    const float* x     = (const float*)d_in[0];
    const int*   ei    = (const int*)d_in[1];
    const int*   batch = (const int*)d_in[2];
    const float* W1    = (const float*)d_in[3];
    const float* b1    = (const float*)d_in[4];
    const float* W2    = (const float*)d_in[5];
    const float* b2    = (const float*)d_in[6];
    const float* gamma = (const float*)d_in[7];
    const float* beta  = (const float*)d_in[8];

    float* z_cat = (float*)d_out;
    float* g_cat = z_cat + (size_t)NNODES * NLAYERS * DIM;

    cudaFuncSetAttribute(k_mlp, cudaFuncAttributeMaxDynamicSharedMemorySize, SMEM_TOT);

    float* aggr;  cudaGetSymbolAddress((void**)&aggr, g_aggr);
    float* hbuf;  cudaGetSymbolAddress((void**)&hbuf, g_h);
    __nv_bfloat16 *bshi, *bslo;
    cudaGetSymbolAddress((void**)&bshi, g_bs_hi);
    cudaGetSymbolAddress((void**)&bslo, g_bs_lo);

    // CSR build + W images
    k_zero_cnt<<<128, 512>>>(g_cat);
    k_hist<<<(NEDGES / 4 + 511) / 512, 512>>>(ei);
    k_chunksum<<<NCHUNK, 1024>>>();
    k_scanchunks<<<1, 128>>>();
    k_scanwrite<<<NCHUNK, 1024>>>();
    k_fill<<<(NEDGES / 4 + 511) / 512, 512>>>(ei);
    k_wconv<<<6, 256>>>(W1, W2);

    const int np_grid  = (NNODES + NP_CH - 1) / NP_CH;
    const int agg_grid = (NNODES * 32 + 255) / 256;

    for (int l = 0; l < NLAYERS; l++) {
        const float* zin = (l == 0) ? x : (z_cat + (size_t)(l - 1) * DIM);
        const int pin = (l == 0) ? DIM : (NLAYERS * DIM);

        k_aggregate<<<agg_grid, 256>>>(zin, pin);
        k_mlp<<<NSMS, 256, SMEM_TOT>>>(
            aggr,
            bshi + (size_t)(l * 2) * DIM * DIM, bslo + (size_t)(l * 2) * DIM * DIM,
            bshi + (size_t)(l * 2 + 1) * DIM * DIM, bslo + (size_t)(l * 2 + 1) * DIM * DIM,
            b1 + (size_t)l * DIM, b2 + (size_t)l * DIM, hbuf, NNODES);
        k_norm_pool<<<np_grid, 256>>>(hbuf, batch,
                                      gamma + (size_t)l * DIM, beta + (size_t)l * DIM,
                                      z_cat + (size_t)l * DIM,
                                      g_cat + (size_t)l * DIM);
    }
}

// round 16
// speedup vs baseline: 1.0411x; 1.0411x over previous
#include <cuda_runtime.h>
#include <cuda_bf16.h>
#include <cstdint>

#define NNODES 100000
#define NEDGES 1600000
#define DIM 128
#define NGRAPHS 128
#define NLAYERS 3
#define BN_EPS 1e-5f
#define NCHUNK ((NNODES + 1023) / 1024)
#define NTILES ((NNODES + 127) / 128)
#define NSMS 148

// ---------------- scratch (static device globals; no allocation) -------------
__device__ float g_aggr[(size_t)NNODES * DIM];
__device__ float g_h[(size_t)NNODES * DIM];
__device__ float g_sum[DIM];
__device__ float g_sumsq[DIM];

__device__ __align__(16) __nv_bfloat16 g_bs_hi[6 * DIM * DIM];
__device__ __align__(16) __nv_bfloat16 g_bs_lo[6 * DIM * DIM];

__device__ int g_cnt[NNODES];
__device__ int g_rowptr[NNODES + 1];
__device__ int g_cur[NNODES];
__device__ int g_srcbuf[NEDGES];
__device__ int g_csum[NCHUNK];
__device__ int g_coff[NCHUNK];

// ---------------- CSR construction -------------------------------------------
__global__ void k_zero_cnt(float* __restrict__ gcat) {
    int i = blockIdx.x * blockDim.x + threadIdx.x;
    int stride = gridDim.x * blockDim.x;
    for (int j = i; j < NNODES; j += stride) g_cnt[j] = 0;
    for (int j = i; j < NGRAPHS * NLAYERS * DIM; j += stride) gcat[j] = 0.f;
    if (blockIdx.x == 0 && threadIdx.x < DIM) {
        g_sum[threadIdx.x] = 0.f;
        g_sumsq[threadIdx.x] = 0.f;
    }
}

__global__ void k_hist(const int* __restrict__ ei) {
    int i = blockIdx.x * blockDim.x + threadIdx.x;
    if (i < NEDGES / 4) {
        int4 d = ((const int4*)(ei + NEDGES))[i];
        atomicAdd(&g_cnt[d.x], 1);
        atomicAdd(&g_cnt[d.y], 1);
        atomicAdd(&g_cnt[d.z], 1);
        atomicAdd(&g_cnt[d.w], 1);
    }
}

__global__ void k_chunksum() {
    __shared__ int wsum[32];
    int i = blockIdx.x * 1024 + threadIdx.x;
    int v = (i < NNODES) ? g_cnt[i] : 0;
    #pragma unroll
    for (int o = 16; o > 0; o >>= 1) v += __shfl_down_sync(~0u, v, o);
    if ((threadIdx.x & 31) == 0) wsum[threadIdx.x >> 5] = v;
    __syncthreads();
    if (threadIdx.x < 32) {
        int s = wsum[threadIdx.x];
        #pragma unroll
        for (int o = 16; o > 0; o >>= 1) s += __shfl_down_sync(~0u, s, o);
        if (threadIdx.x == 0) g_csum[blockIdx.x] = s;
    }
}

__global__ void k_scanchunks() {
    __shared__ int sh[4];
    const int tid = threadIdx.x;
    const int lane = tid & 31;
    const int wid = tid >> 5;
    int v = (tid < NCHUNK) ? g_csum[tid] : 0;
    int x = v;
    #pragma unroll
    for (int o = 1; o < 32; o <<= 1) {
        int t = __shfl_up_sync(~0u, x, o);
        if (lane >= o) x += t;
    }
    if (lane == 31) sh[wid] = x;
    __syncthreads();
    int base = 0;
    #pragma unroll
    for (int w = 0; w < 4; w++) if (w < wid) base += sh[w];
    int excl = base + x - v;
    if (tid < NCHUNK) g_coff[tid] = excl;
    if (tid == 127) g_rowptr[NNODES] = base + x;
}

__global__ void k_scanwrite() {
    __shared__ int wsum[32];
    const int tid = threadIdx.x;
    const int lane = tid & 31;
    const int wid = tid >> 5;
    int i = blockIdx.x * 1024 + tid;
    int v = (i < NNODES) ? g_cnt[i] : 0;
    int x = v;
    #pragma unroll
    for (int o = 1; o < 32; o <<= 1) {
        int t = __shfl_up_sync(~0u, x, o);
        if (lane >= o) x += t;
    }
    if (lane == 31) wsum[wid] = x;
    __syncthreads();
    if (wid == 0) {
        int s = wsum[lane];
        #pragma unroll
        for (int o = 1; o < 32; o <<= 1) {
            int t = __shfl_up_sync(~0u, s, o);
            if (lane >= o) s += t;
        }
        wsum[lane] = s;
    }
    __syncthreads();
    int excl = g_coff[blockIdx.x] + x - v + (wid > 0 ? wsum[wid - 1] : 0);
    if (i < NNODES) { g_rowptr[i] = excl; g_cur[i] = excl; }
}

__global__ void k_fill(const int* __restrict__ ei) {
    int i = blockIdx.x * blockDim.x + threadIdx.x;
    if (i < NEDGES / 4) {
        int4 s = ((const int4*)ei)[i];
        int4 d = ((const int4*)(ei + NEDGES))[i];
        int p0 = atomicAdd(&g_cur[d.x], 1); g_srcbuf[p0] = s.x;
        int p1 = atomicAdd(&g_cur[d.y], 1); g_srcbuf[p1] = s.y;
        int p2 = atomicAdd(&g_cur[d.z], 1); g_srcbuf[p2] = s.z;
        int p3 = atomicAdd(&g_cur[d.w], 1); g_srcbuf[p3] = s.w;
    }
}

// ---------------- W^T -> bf16 hi/lo Bs[n][k] -----------------------------------
__global__ void k_wconv(const float* __restrict__ W1, const float* __restrict__ W2) {
    int which = blockIdx.x;
    int layer = which >> 1;
    const float* W = (which & 1) ? (W2 + (size_t)layer * DIM * DIM)
                                 : (W1 + (size_t)layer * DIM * DIM);
    __nv_bfloat16* hi = g_bs_hi + (size_t)which * DIM * DIM;
    __nv_bfloat16* lo = g_bs_lo + (size_t)which * DIM * DIM;
    for (int e = threadIdx.x; e < DIM * DIM; e += blockDim.x) {
        int n = e >> 7, k = e & 127;
        float x = W[k * DIM + n];
        __nv_bfloat16 h = __float2bfloat16(x);
        __nv_bfloat16 l = __float2bfloat16(x - __bfloat162float(h));
        hi[e] = h;
        lo[e] = l;
    }
}

// ---------------- gather aggregation (4-way, warp per node) --------------------
__global__ void k_aggregate(const float* __restrict__ zin, int pin) {
    if (blockIdx.x == 0 && threadIdx.x < DIM) {
        g_sum[threadIdx.x] = 0.f;
        g_sumsq[threadIdx.x] = 0.f;
    }
    const int lane = threadIdx.x & 31;
    const int w = (blockIdx.x * blockDim.x + threadIdx.x) >> 5;
    if (w >= NNODES) return;
    const int c = lane * 4;
    const int beg = g_rowptr[w];
    const int end = g_rowptr[w + 1];
    float4 a0 = *(const float4*)(zin + (size_t)w * pin + c);
    float4 a1 = make_float4(0.f, 0.f, 0.f, 0.f);
    float4 a2 = a1, a3 = a1;
    int e = beg;
    for (; e + 4 <= end; e += 4) {
        int s0 = __ldg(g_srcbuf + e), s1 = __ldg(g_srcbuf + e + 1);
        int s2 = __ldg(g_srcbuf + e + 2), s3 = __ldg(g_srcbuf + e + 3);
        float4 v0 = *(const float4*)(zin + (size_t)s0 * pin + c);
        float4 v1 = *(const float4*)(zin + (size_t)s1 * pin + c);
        float4 v2 = *(const float4*)(zin + (size_t)s2 * pin + c);
        float4 v3 = *(const float4*)(zin + (size_t)s3 * pin + c);
        a0.x += v0.x; a0.y += v0.y; a0.z += v0.z; a0.w += v0.w;
        a1.x += v1.x; a1.y += v1.y; a1.z += v1.z; a1.w += v1.w;
        a2.x += v2.x; a2.y += v2.y; a2.z += v2.z; a2.w += v2.w;
        a3.x += v3.x; a3.y += v3.y; a3.z += v3.z; a3.w += v3.w;
    }
    for (; e < end; e++) {
        int s = __ldg(g_srcbuf + e);
        float4 v = *(const float4*)(zin + (size_t)s * pin + c);
        a0.x += v.x; a0.y += v.y; a0.z += v.z; a0.w += v.w;
    }
    a0.x += a1.x + a2.x + a3.x;
    a0.y += a1.y + a2.y + a3.y;
    a0.z += a1.z + a2.z + a3.z;
    a0.w += a1.w + a2.w + a3.w;
    *(float4*)(g_aggr + (size_t)w * DIM + c) = a0;
}

// ---------------- persistent fused 2-GEMM MLP + BN stats ----------------------
#define PITCHB 272
#define SM_AHI 0
#define SM_ALO (SM_AHI + 128 * PITCHB)
#define SM_B1HI (SM_ALO + 128 * PITCHB)
#define SM_B1LO (SM_B1HI + 128 * PITCHB)
#define SM_B2HI (SM_B1LO + 128 * PITCHB)
#define SM_B2LO (SM_B2HI + 128 * PITCHB)
#define SM_SUM (SM_B2LO + 128 * PITCHB)       // float [8][128]
#define SM_SQ  (SM_SUM + 8 * 128 * 4)
#define SM_BS1 (SM_SQ + 8 * 128 * 4)
#define SM_BS2 (SM_BS1 + 512)
#define SMEM_TOT (SM_BS2 + 512)

#define MMA16816(c, a0, a1, a2, a3, b0, b1) \
    asm volatile("mma.sync.aligned.m16n8k16.row.col.f32.bf16.bf16.f32 " \
        "{%0,%1,%2,%3}, {%4,%5,%6,%7}, {%8,%9}, {%0,%1,%2,%3};" \
        : "+f"((c)[0]), "+f"((c)[1]), "+f"((c)[2]), "+f"((c)[3]) \
        : "r"(a0), "r"(a1), "r"(a2), "r"(a3), "r"(b0), "r"(b1))

__device__ __forceinline__ uint32_t pack_hi2(float x0, float x1, uint32_t& lo) {
    __nv_bfloat16 h0 = __float2bfloat16(x0);
    __nv_bfloat16 h1 = __float2bfloat16(x1);
    __nv_bfloat16 l0 = __float2bfloat16(x0 - __bfloat162float(h0));
    __nv_bfloat16 l1 = __float2bfloat16(x1 - __bfloat162float(h1));
    lo = (uint32_t)__bfloat16_as_ushort(l0) | ((uint32_t)__bfloat16_as_ushort(l1) << 16);
    return (uint32_t)__bfloat16_as_ushort(h0) | ((uint32_t)__bfloat16_as_ushort(h1) << 16);
}

__device__ __forceinline__ void mma_3pass(char* smem, int bhi_off, int blo_off,
                                          int m0, int n0, int g, int t,
                                          float c[2][8][4]) {
    #pragma unroll
    for (int mt = 0; mt < 2; mt++)
        #pragma unroll
        for (int nt = 0; nt < 8; nt++)
            #pragma unroll
            for (int q = 0; q < 4; q++) c[mt][nt][q] = 0.f;
    #pragma unroll
    for (int p = 0; p < 3; p++) {
        const char* As = smem + (p == 2 ? SM_ALO : SM_AHI);
        const char* Bs = smem + (p == 1 ? blo_off : bhi_off);
        #pragma unroll
        for (int ks = 0; ks < 8; ks++) {
            const int kb = ks * 16;
            uint32_t a[2][4];
            #pragma unroll
            for (int mt = 0; mt < 2; mt++) {
                const char* pr = As + (m0 + mt * 16 + g) * PITCHB + (kb + 2 * t) * 2;
                a[mt][0] = *(const uint32_t*)pr;
                a[mt][1] = *(const uint32_t*)(pr + 8 * PITCHB);
                a[mt][2] = *(const uint32_t*)(pr + 16);
                a[mt][3] = *(const uint32_t*)(pr + 8 * PITCHB + 16);
            }
            #pragma unroll
            for (int nt = 0; nt < 8; nt++) {
                const char* pb = Bs + (n0 + nt * 8 + g) * PITCHB + (kb + 2 * t) * 2;
                uint32_t b0 = *(const uint32_t*)pb;
                uint32_t b1 = *(const uint32_t*)(pb + 16);
                MMA16816(c[0][nt], a[0][0], a[0][1], a[0][2], a[0][3], b0, b1);
                MMA16816(c[1][nt], a[1][0], a[1][1], a[1][2], a[1][3], b0, b1);
            }
        }
    }
}

__global__ void __launch_bounds__(256, 1)
k_mlp(const float* __restrict__ Afp,
      const __nv_bfloat16* __restrict__ B1hi, const __nv_bfloat16* __restrict__ B1lo,
      const __nv_bfloat16* __restrict__ B2hi, const __nv_bfloat16* __restrict__ B2lo,
      const float* __restrict__ bias1, const float* __restrict__ bias2,
      float* __restrict__ outh, int nrows) {
    extern __shared__ char smem[];
    const int tid = threadIdx.x;
    const int wid = tid >> 5;
    const int lane = tid & 31;
    const int g = lane >> 2;
    const int t = lane & 3;

    // one-time setup
    {
        float* z = (float*)(smem + SM_SUM);
        #pragma unroll
        for (int i = 0; i < 8; i++) z[tid + i * 256] = 0.f;
        if (tid < DIM) {
            ((float*)(smem + SM_BS1))[tid] = bias1[tid];
            ((float*)(smem + SM_BS2))[tid] = bias2[tid];
        }
        const uint4* s1h = (const uint4*)B1hi;
        const uint4* s1l = (const uint4*)B1lo;
        const uint4* s2h = (const uint4*)B2hi;
        const uint4* s2l = (const uint4*)B2lo;
        #pragma unroll
        for (int i = 0; i < 8; i++) {
            int idx = tid + i * 256;
            int r = idx >> 4, k = (idx & 15) * 8;
            int off = r * PITCHB + k * 2;
            *(uint4*)(smem + SM_B1HI + off) = s1h[idx];
            *(uint4*)(smem + SM_B1LO + off) = s1l[idx];
            *(uint4*)(smem + SM_B2HI + off) = s2h[idx];
            *(uint4*)(smem + SM_B2LO + off) = s2l[idx];
        }
    }

    const int m0 = (wid >> 1) * 32;
    const int n0 = (wid & 1) * 64;
    float c[2][8][4];

    for (int tile = blockIdx.x; tile < NTILES; tile += gridDim.x) {
        const int row0 = tile * 128;

        // load + split A (fp32 -> bf16 hi/lo planes)
        #pragma unroll
        for (int i = 0; i < 16; i++) {
            int idx = tid + i * 256;
            int r = idx >> 5, k = (idx & 31) * 4;
            int gr = row0 + r;
            float4 v = make_float4(0.f, 0.f, 0.f, 0.f);
            if (gr < nrows) v = *(const float4*)(Afp + (size_t)gr * DIM + k);
            uint32_t l0, l1, h0, h1;
            h0 = pack_hi2(v.x, v.y, l0);
            h1 = pack_hi2(v.z, v.w, l1);
            *(uint2*)(smem + SM_AHI + r * PITCHB + k * 2) = make_uint2(h0, h1);
            *(uint2*)(smem + SM_ALO + r * PITCHB + k * 2) = make_uint2(l0, l1);
        }
        __syncthreads();

        // ---- GEMM1 ----
        mma_3pass(smem, SM_B1HI, SM_B1LO, m0, n0, g, t, c);
        __syncthreads();

        // epilogue1: bias1+relu -> hi/lo back into A planes
        #pragma unroll
        for (int nt = 0; nt < 8; nt++) {
            const int ce = n0 + nt * 8 + 2 * t;
            const float be = ((const float*)(smem + SM_BS1))[ce];
            const float bo = ((const float*)(smem + SM_BS1))[ce + 1];
            #pragma unroll
            for (int mt = 0; mt < 2; mt++) {
                #pragma unroll
                for (int rr = 0; rr < 2; rr++) {
                    const int r = m0 + mt * 16 + g + rr * 8;
                    float ve = fmaxf(c[mt][nt][rr * 2] + be, 0.f);
                    float vo = fmaxf(c[mt][nt][rr * 2 + 1] + bo, 0.f);
                    uint32_t lo;
                    uint32_t hi = pack_hi2(ve, vo, lo);
                    *(uint32_t*)(smem + SM_AHI + r * PITCHB + ce * 2) = hi;
                    *(uint32_t*)(smem + SM_ALO + r * PITCHB + ce * 2) = lo;
                }
            }
        }
        __syncthreads();

        // ---- GEMM2 ----
        mma_3pass(smem, SM_B2HI, SM_B2LO, m0, n0, g, t, c);

        // epilogue2: bias2+relu -> fp32 out + stats
        #pragma unroll
        for (int nt = 0; nt < 8; nt++) {
            const int ce = n0 + nt * 8 + 2 * t;
            const float be = ((const float*)(smem + SM_BS2))[ce];
            const float bo = ((const float*)(smem + SM_BS2))[ce + 1];
            float se = 0.f, so = 0.f, qe = 0.f, qo = 0.f;
            #pragma unroll
            for (int mt = 0; mt < 2; mt++) {
                #pragma unroll
                for (int rr = 0; rr < 2; rr++) {
                    const int gr = row0 + m0 + mt * 16 + g + rr * 8;
                    float ve = fmaxf(c[mt][nt][rr * 2] + be, 0.f);
                    float vo = fmaxf(c[mt][nt][rr * 2 + 1] + bo, 0.f);
                    if (gr >= nrows) { ve = 0.f; vo = 0.f; }
                    se += ve; so += vo;
                    qe += ve * ve; qo += vo * vo;
                    if (gr < nrows)
                        *(float2*)(outh + (size_t)gr * DIM + ce) = make_float2(ve, vo);
                }
            }
            #pragma unroll
            for (int o = 4; o < 32; o <<= 1) {
                se += __shfl_xor_sync(~0u, se, o);
                so += __shfl_xor_sync(~0u, so, o);
                qe += __shfl_xor_sync(~0u, qe, o);
                qo += __shfl_xor_sync(~0u, qo, o);
            }
            if (g == 0) {
                float* ps = (float*)(smem + SM_SUM) + wid * 128;
                float* pq = (float*)(smem + SM_SQ) + wid * 128;
                ps[ce] = se; ps[ce + 1] = so;
                pq[ce] = qe; pq[ce + 1] = qo;
            }
        }
        __syncthreads();

        if (tid < 128) {
            const float* ps = (const float*)(smem + SM_SUM);
            float s = 0.f;
            #pragma unroll
            for (int w = 0; w < 8; w++) s += ps[w * 128 + tid];
            atomicAdd(&g_sum[tid], s);
        } else {
            const float* pq = (const float*)(smem + SM_SQ);
            const int f = tid - 128;
            float s = 0.f;
            #pragma unroll
            for (int w = 0; w < 8; w++) s += pq[w * 128 + f];
            atomicAdd(&g_sumsq[f], s);
        }
        __syncthreads();
    }
}

// ---------------- normalize + z_cat slice + graph add-pool (float4) -----------
#define NP_CH 128
__global__ void k_norm_pool(const float* __restrict__ h,
                            const int* __restrict__ batch,
                            const float* __restrict__ gamma,
                            const float* __restrict__ beta,
                            float* __restrict__ zout,
                            float* __restrict__ gout) {
    __shared__ float s_sc[DIM], s_sh[DIM];
    if (threadIdx.x < DIM) {
        int f = threadIdx.x;
        float mean = g_sum[f] * (1.0f / NNODES);
        float var = g_sumsq[f] * (1.0f / NNODES) - mean * mean;
        float inv = rsqrtf(var + BN_EPS);
        float sc = gamma[f] * inv;
        s_sc[f] = sc;
        s_sh[f] = beta[f] - mean * sc;
    }
    __syncthreads();

    const int f4 = (threadIdx.x & 31) * 4;
    const int ln = threadIdx.x >> 5;
    const int r0 = blockIdx.x * NP_CH;
    const int rend = min(r0 + NP_CH, NNODES);
    const float4 sc = *(const float4*)(s_sc + f4);
    const float4 sh = *(const float4*)(s_sh + f4);
    float4 acc = make_float4(0.f, 0.f, 0.f, 0.f);
    int cur = -1;
    for (int r = r0 + ln; r < rend; r += 8) {
        float4 x = *(const float4*)(h + (size_t)r * DIM + f4);
        float4 v;
        v.x = fmaf(x.x, sc.x, sh.x);
        v.y = fmaf(x.y, sc.y, sh.y);
        v.z = fmaf(x.z, sc.z, sh.z);
        v.w = fmaf(x.w, sc.w, sh.w);
        *(float4*)(zout + (size_t)r * (NLAYERS * DIM) + f4) = v;
        int b = batch[r];
        if (b != cur) {
            if (cur >= 0) {
                float* p = gout + (size_t)cur * (NLAYERS * DIM) + f4;
                atomicAdd(p, acc.x); atomicAdd(p + 1, acc.y);
                atomicAdd(p + 2, acc.z); atomicAdd(p + 3, acc.w);
            }
            cur = b;
            acc = v;
        } else {
            acc.x += v.x; acc.y += v.y; acc.z += v.z; acc.w += v.w;
        }
    }
    if (cur >= 0) {
        float* p = gout + (size_t)cur * (NLAYERS * DIM) + f4;
        atomicAdd(p, acc.x); atomicAdd(p + 1, acc.y);
        atomicAdd(p + 2, acc.z); atomicAdd(p + 3, acc.w);
    }
}

// ---------------- launch -------------------------------------------------------
extern "C" void kernel_launch(void* const* d_in, const int* in_sizes, int n_in,
                              void* d_out, int out_size) {
    const float* x     = (const float*)d_in[0];
    const int*   ei    = (const int*)d_in[1];
    const int*   batch = (const int*)d_in[2];
    const float* W1    = (const float*)d_in[3];
    const float* b1    = (const float*)d_in[4];
    const float* W2    = (const float*)d_in[5];
    const float* b2    = (const float*)d_in[6];
    const float* gamma = (const float*)d_in[7];
    const float* beta  = (const float*)d_in[8];

    float* z_cat = (float*)d_out;
    float* g_cat = z_cat + (size_t)NNODES * NLAYERS * DIM;

    cudaFuncSetAttribute(k_mlp, cudaFuncAttributeMaxDynamicSharedMemorySize, SMEM_TOT);

    float* aggr;  cudaGetSymbolAddress((void**)&aggr, g_aggr);
    float* hbuf;  cudaGetSymbolAddress((void**)&hbuf, g_h);
    __nv_bfloat16 *bshi, *bslo;
    cudaGetSymbolAddress((void**)&bshi, g_bs_hi);
    cudaGetSymbolAddress((void**)&bslo, g_bs_lo);

    // CSR build + W images
    k_zero_cnt<<<128, 512>>>(g_cat);
    k_hist<<<(NEDGES / 4 + 511) / 512, 512>>>(ei);
    k_chunksum<<<NCHUNK, 1024>>>();
    k_scanchunks<<<1, 128>>>();
    k_scanwrite<<<NCHUNK, 1024>>>();
    k_fill<<<(NEDGES / 4 + 511) / 512, 512>>>(ei);
    k_wconv<<<6, 256>>>(W1, W2);

    const int np_grid  = (NNODES + NP_CH - 1) / NP_CH;
    const int agg_grid = (NNODES * 32 + 255) / 256;

    for (int l = 0; l < NLAYERS; l++) {
        const float* zin = (l == 0) ? x : (z_cat + (size_t)(l - 1) * DIM);
        const int pin = (l == 0) ? DIM : (NLAYERS * DIM);

        k_aggregate<<<agg_grid, 256>>>(zin, pin);
        k_mlp<<<NSMS, 256, SMEM_TOT>>>(
            aggr,
            bshi + (size_t)(l * 2) * DIM * DIM, bslo + (size_t)(l * 2) * DIM * DIM,
            bshi + (size_t)(l * 2 + 1) * DIM * DIM, bslo + (size_t)(l * 2 + 1) * DIM * DIM,
            b1 + (size_t)l * DIM, b2 + (size_t)l * DIM, hbuf, NNODES);
        k_norm_pool<<<np_grid, 256>>>(hbuf, batch,
                                      gamma + (size_t)l * DIM, beta + (size_t)l * DIM,
                                      z_cat + (size_t)l * DIM,
                                      g_cat + (size_t)l * DIM);
    }
}

// round 17
// speedup vs baseline: 1.0717x; 1.0294x over previous
#include <cuda_runtime.h>
#include <cuda_bf16.h>
#include <cstdint>

#define NNODES 100000
#define NEDGES 1600000
#define DIM 128
#define NGRAPHS 128
#define NLAYERS 3
#define BN_EPS 1e-5f
#define NCHUNK ((NNODES + 1023) / 1024)
#define NTILES ((NNODES + 127) / 128)
#define NROWS_PAD (NTILES * 128)
#define NSMS 148

// ---------------- scratch (static device globals; no allocation) -------------
__device__ float g_h[(size_t)NNODES * DIM];
__device__ float g_sum[DIM];
__device__ float g_sumsq[DIM];

// aggregate output, pre-split bf16 hi/lo planes (linear [row][128])
__device__ __align__(16) __nv_bfloat16 g_a_hi[(size_t)NROWS_PAD * DIM];
__device__ __align__(16) __nv_bfloat16 g_a_lo[(size_t)NROWS_PAD * DIM];

__device__ __align__(16) __nv_bfloat16 g_bs_hi[6 * DIM * DIM];
__device__ __align__(16) __nv_bfloat16 g_bs_lo[6 * DIM * DIM];

__device__ int g_cnt[NNODES];
__device__ int g_rowptr[NNODES + 1];
__device__ int g_cur[NNODES];
__device__ int g_srcbuf[NEDGES];
__device__ int g_csum[NCHUNK];
__device__ int g_coff[NCHUNK];

__device__ __forceinline__ uint32_t pack_hi2(float x0, float x1, uint32_t& lo) {
    __nv_bfloat16 h0 = __float2bfloat16(x0);
    __nv_bfloat16 h1 = __float2bfloat16(x1);
    __nv_bfloat16 l0 = __float2bfloat16(x0 - __bfloat162float(h0));
    __nv_bfloat16 l1 = __float2bfloat16(x1 - __bfloat162float(h1));
    lo = (uint32_t)__bfloat16_as_ushort(l0) | ((uint32_t)__bfloat16_as_ushort(l1) << 16);
    return (uint32_t)__bfloat16_as_ushort(h0) | ((uint32_t)__bfloat16_as_ushort(h1) << 16);
}

// ---------------- CSR construction -------------------------------------------
__global__ void k_zero_cnt(float* __restrict__ gcat) {
    int i = blockIdx.x * blockDim.x + threadIdx.x;
    int stride = gridDim.x * blockDim.x;
    for (int j = i; j < NNODES; j += stride) g_cnt[j] = 0;
    for (int j = i; j < NGRAPHS * NLAYERS * DIM; j += stride) gcat[j] = 0.f;
    // zero pad tail of the bf16 planes (rows NNODES..NROWS_PAD)
    const int pad0 = NNODES * DIM;
    const int padn = (NROWS_PAD - NNODES) * DIM;
    for (int j = i; j < padn; j += stride) {
        g_a_hi[pad0 + j] = __ushort_as_bfloat16(0);
        g_a_lo[pad0 + j] = __ushort_as_bfloat16(0);
    }
    if (blockIdx.x == 0 && threadIdx.x < DIM) {
        g_sum[threadIdx.x] = 0.f;
        g_sumsq[threadIdx.x] = 0.f;
    }
}

__global__ void k_hist(const int* __restrict__ ei) {
    int i = blockIdx.x * blockDim.x + threadIdx.x;
    if (i < NEDGES / 4) {
        int4 d = ((const int4*)(ei + NEDGES))[i];
        atomicAdd(&g_cnt[d.x], 1);
        atomicAdd(&g_cnt[d.y], 1);
        atomicAdd(&g_cnt[d.z], 1);
        atomicAdd(&g_cnt[d.w], 1);
    }
}

__global__ void k_chunksum() {
    __shared__ int wsum[32];
    int i = blockIdx.x * 1024 + threadIdx.x;
    int v = (i < NNODES) ? g_cnt[i] : 0;
    #pragma unroll
    for (int o = 16; o > 0; o >>= 1) v += __shfl_down_sync(~0u, v, o);
    if ((threadIdx.x & 31) == 0) wsum[threadIdx.x >> 5] = v;
    __syncthreads();
    if (threadIdx.x < 32) {
        int s = wsum[threadIdx.x];
        #pragma unroll
        for (int o = 16; o > 0; o >>= 1) s += __shfl_down_sync(~0u, s, o);
        if (threadIdx.x == 0) g_csum[blockIdx.x] = s;
    }
}

__global__ void k_scanchunks() {
    __shared__ int sh[4];
    const int tid = threadIdx.x;
    const int lane = tid & 31;
    const int wid = tid >> 5;
    int v = (tid < NCHUNK) ? g_csum[tid] : 0;
    int x = v;
    #pragma unroll
    for (int o = 1; o < 32; o <<= 1) {
        int t = __shfl_up_sync(~0u, x, o);
        if (lane >= o) x += t;
    }
    if (lane == 31) sh[wid] = x;
    __syncthreads();
    int base = 0;
    #pragma unroll
    for (int w = 0; w < 4; w++) if (w < wid) base += sh[w];
    int excl = base + x - v;
    if (tid < NCHUNK) g_coff[tid] = excl;
    if (tid == 127) g_rowptr[NNODES] = base + x;
}

__global__ void k_scanwrite() {
    __shared__ int wsum[32];
    const int tid = threadIdx.x;
    const int lane = tid & 31;
    const int wid = tid >> 5;
    int i = blockIdx.x * 1024 + tid;
    int v = (i < NNODES) ? g_cnt[i] : 0;
    int x = v;
    #pragma unroll
    for (int o = 1; o < 32; o <<= 1) {
        int t = __shfl_up_sync(~0u, x, o);
        if (lane >= o) x += t;
    }
    if (lane == 31) wsum[wid] = x;
    __syncthreads();
    if (wid == 0) {
        int s = wsum[lane];
        #pragma unroll
        for (int o = 1; o < 32; o <<= 1) {
            int t = __shfl_up_sync(~0u, s, o);
            if (lane >= o) s += t;
        }
        wsum[lane] = s;
    }
    __syncthreads();
    int excl = g_coff[blockIdx.x] + x - v + (wid > 0 ? wsum[wid - 1] : 0);
    if (i < NNODES) { g_rowptr[i] = excl; g_cur[i] = excl; }
}

__global__ void k_fill(const int* __restrict__ ei) {
    int i = blockIdx.x * blockDim.x + threadIdx.x;
    if (i < NEDGES / 4) {
        int4 s = ((const int4*)ei)[i];
        int4 d = ((const int4*)(ei + NEDGES))[i];
        int p0 = atomicAdd(&g_cur[d.x], 1); g_srcbuf[p0] = s.x;
        int p1 = atomicAdd(&g_cur[d.y], 1); g_srcbuf[p1] = s.y;
        int p2 = atomicAdd(&g_cur[d.z], 1); g_srcbuf[p2] = s.z;
        int p3 = atomicAdd(&g_cur[d.w], 1); g_srcbuf[p3] = s.w;
    }
}

// ---------------- W^T -> bf16 hi/lo Bs[n][k] -----------------------------------
__global__ void k_wconv(const float* __restrict__ W1, const float* __restrict__ W2) {
    int which = blockIdx.x;
    int layer = which >> 1;
    const float* W = (which & 1) ? (W2 + (size_t)layer * DIM * DIM)
                                 : (W1 + (size_t)layer * DIM * DIM);
    __nv_bfloat16* hi = g_bs_hi + (size_t)which * DIM * DIM;
    __nv_bfloat16* lo = g_bs_lo + (size_t)which * DIM * DIM;
    for (int e = threadIdx.x; e < DIM * DIM; e += blockDim.x) {
        int n = e >> 7, k = e & 127;
        float x = W[k * DIM + n];
        __nv_bfloat16 h = __float2bfloat16(x);
        __nv_bfloat16 l = __float2bfloat16(x - __bfloat162float(h));
        hi[e] = h;
        lo[e] = l;
    }
}

// ---------------- gather aggregation (4-way) + bf16 hi/lo split output ---------
__global__ void k_aggregate(const float* __restrict__ zin, int pin) {
    if (blockIdx.x == 0 && threadIdx.x < DIM) {
        g_sum[threadIdx.x] = 0.f;
        g_sumsq[threadIdx.x] = 0.f;
    }
    const int lane = threadIdx.x & 31;
    const int w = (blockIdx.x * blockDim.x + threadIdx.x) >> 5;
    if (w >= NNODES) return;
    const int c = lane * 4;
    const int beg = g_rowptr[w];
    const int end = g_rowptr[w + 1];
    float4 a0 = *(const float4*)(zin + (size_t)w * pin + c);
    float4 a1 = make_float4(0.f, 0.f, 0.f, 0.f);
    float4 a2 = a1, a3 = a1;
    int e = beg;
    for (; e + 4 <= end; e += 4) {
        int s0 = __ldg(g_srcbuf + e), s1 = __ldg(g_srcbuf + e + 1);
        int s2 = __ldg(g_srcbuf + e + 2), s3 = __ldg(g_srcbuf + e + 3);
        float4 v0 = *(const float4*)(zin + (size_t)s0 * pin + c);
        float4 v1 = *(const float4*)(zin + (size_t)s1 * pin + c);
        float4 v2 = *(const float4*)(zin + (size_t)s2 * pin + c);
        float4 v3 = *(const float4*)(zin + (size_t)s3 * pin + c);
        a0.x += v0.x; a0.y += v0.y; a0.z += v0.z; a0.w += v0.w;
        a1.x += v1.x; a1.y += v1.y; a1.z += v1.z; a1.w += v1.w;
        a2.x += v2.x; a2.y += v2.y; a2.z += v2.z; a2.w += v2.w;
        a3.x += v3.x; a3.y += v3.y; a3.z += v3.z; a3.w += v3.w;
    }
    for (; e < end; e++) {
        int s = __ldg(g_srcbuf + e);
        float4 v = *(const float4*)(zin + (size_t)s * pin + c);
        a0.x += v.x; a0.y += v.y; a0.z += v.z; a0.w += v.w;
    }
    a0.x += a1.x + a2.x + a3.x;
    a0.y += a1.y + a2.y + a3.y;
    a0.z += a1.z + a2.z + a3.z;
    a0.w += a1.w + a2.w + a3.w;
    // split fp32 -> bf16 hi/lo, coalesced uint2 stores (8B/lane per plane)
    uint32_t lo0, lo1;
    uint32_t h0 = pack_hi2(a0.x, a0.y, lo0);
    uint32_t h1 = pack_hi2(a0.z, a0.w, lo1);
    *(uint2*)((char*)g_a_hi + ((size_t)w * DIM + c) * 2) = make_uint2(h0, h1);
    *(uint2*)((char*)g_a_lo + ((size_t)w * DIM + c) * 2) = make_uint2(lo0, lo1);
}

// ---------------- persistent fused 2-GEMM MLP + BN stats ----------------------
#define PITCHB 272
#define SM_AHI 0
#define SM_ALO (SM_AHI + 128 * PITCHB)
#define SM_B1HI (SM_ALO + 128 * PITCHB)
#define SM_B1LO (SM_B1HI + 128 * PITCHB)
#define SM_B2HI (SM_B1LO + 128 * PITCHB)
#define SM_B2LO (SM_B2HI + 128 * PITCHB)
#define SM_SUM (SM_B2LO + 128 * PITCHB)       // float [8][128]
#define SM_SQ  (SM_SUM + 8 * 128 * 4)
#define SM_BS1 (SM_SQ + 8 * 128 * 4)
#define SM_BS2 (SM_BS1 + 512)
#define SMEM_TOT (SM_BS2 + 512)

#define MMA16816(c, a0, a1, a2, a3, b0, b1) \
    asm volatile("mma.sync.aligned.m16n8k16.row.col.f32.bf16.bf16.f32 " \
        "{%0,%1,%2,%3}, {%4,%5,%6,%7}, {%8,%9}, {%0,%1,%2,%3};" \
        : "+f"((c)[0]), "+f"((c)[1]), "+f"((c)[2]), "+f"((c)[3]) \
        : "r"(a0), "r"(a1), "r"(a2), "r"(a3), "r"(b0), "r"(b1))

__device__ __forceinline__ void mma_3pass(char* smem, int bhi_off, int blo_off,
                                          int m0, int n0, int g, int t,
                                          float c[2][8][4]) {
    #pragma unroll
    for (int mt = 0; mt < 2; mt++)
        #pragma unroll
        for (int nt = 0; nt < 8; nt++)
            #pragma unroll
            for (int q = 0; q < 4; q++) c[mt][nt][q] = 0.f;
    #pragma unroll
    for (int p = 0; p < 3; p++) {
        const char* As = smem + (p == 2 ? SM_ALO : SM_AHI);
        const char* Bs = smem + (p == 1 ? blo_off : bhi_off);
        #pragma unroll
        for (int ks = 0; ks < 8; ks++) {
            const int kb = ks * 16;
            uint32_t a[2][4];
            #pragma unroll
            for (int mt = 0; mt < 2; mt++) {
                const char* pr = As + (m0 + mt * 16 + g) * PITCHB + (kb + 2 * t) * 2;
                a[mt][0] = *(const uint32_t*)pr;
                a[mt][1] = *(const uint32_t*)(pr + 8 * PITCHB);
                a[mt][2] = *(const uint32_t*)(pr + 16);
                a[mt][3] = *(const uint32_t*)(pr + 8 * PITCHB + 16);
            }
            #pragma unroll
            for (int nt = 0; nt < 8; nt++) {
                const char* pb = Bs + (n0 + nt * 8 + g) * PITCHB + (kb + 2 * t) * 2;
                uint32_t b0 = *(const uint32_t*)pb;
                uint32_t b1 = *(const uint32_t*)(pb + 16);
                MMA16816(c[0][nt], a[0][0], a[0][1], a[0][2], a[0][3], b0, b1);
                MMA16816(c[1][nt], a[1][0], a[1][1], a[1][2], a[1][3], b0, b1);
            }
        }
    }
}

__global__ void __launch_bounds__(256, 1)
k_mlp(const __nv_bfloat16* __restrict__ Ahi, const __nv_bfloat16* __restrict__ Alo,
      const __nv_bfloat16* __restrict__ B1hi, const __nv_bfloat16* __restrict__ B1lo,
      const __nv_bfloat16* __restrict__ B2hi, const __nv_bfloat16* __restrict__ B2lo,
      const float* __restrict__ bias1, const float* __restrict__ bias2,
      float* __restrict__ outh, int nrows) {
    extern __shared__ char smem[];
    const int tid = threadIdx.x;
    const int wid = tid >> 5;
    const int lane = tid & 31;
    const int g = lane >> 2;
    const int t = lane & 3;

    // one-time setup
    {
        float* z = (float*)(smem + SM_SUM);
        #pragma unroll
        for (int i = 0; i < 8; i++) z[tid + i * 256] = 0.f;
        if (tid < DIM) {
            ((float*)(smem + SM_BS1))[tid] = bias1[tid];
            ((float*)(smem + SM_BS2))[tid] = bias2[tid];
        }
        const uint4* s1h = (const uint4*)B1hi;
        const uint4* s1l = (const uint4*)B1lo;
        const uint4* s2h = (const uint4*)B2hi;
        const uint4* s2l = (const uint4*)B2lo;
        #pragma unroll
        for (int i = 0; i < 8; i++) {
            int idx = tid + i * 256;
            int r = idx >> 4, k = (idx & 15) * 8;
            int off = r * PITCHB + k * 2;
            *(uint4*)(smem + SM_B1HI + off) = s1h[idx];
            *(uint4*)(smem + SM_B1LO + off) = s1l[idx];
            *(uint4*)(smem + SM_B2HI + off) = s2h[idx];
            *(uint4*)(smem + SM_B2LO + off) = s2l[idx];
        }
    }

    const int m0 = (wid >> 1) * 32;
    const int n0 = (wid & 1) * 64;
    float c[2][8][4];

    for (int tile = blockIdx.x; tile < NTILES; tile += gridDim.x) {
        const int row0 = tile * 128;

        // A copy: verbatim bf16 planes -> smem (no conversion, loads batch freely)
        {
            const uint4* ah = (const uint4*)(Ahi + (size_t)row0 * DIM);
            const uint4* al = (const uint4*)(Alo + (size_t)row0 * DIM);
            #pragma unroll
            for (int i = 0; i < 8; i++) {
                int idx = tid + i * 256;
                int r = idx >> 4, k = (idx & 15) * 8;
                int off = r * PITCHB + k * 2;
                *(uint4*)(smem + SM_AHI + off) = ah[idx];
                *(uint4*)(smem + SM_ALO + off) = al[idx];
            }
        }
        __syncthreads();

        // ---- GEMM1 ----
        mma_3pass(smem, SM_B1HI, SM_B1LO, m0, n0, g, t, c);
        __syncthreads();

        // epilogue1: bias1+relu -> hi/lo back into A planes
        #pragma unroll
        for (int nt = 0; nt < 8; nt++) {
            const int ce = n0 + nt * 8 + 2 * t;
            const float be = ((const float*)(smem + SM_BS1))[ce];
            const float bo = ((const float*)(smem + SM_BS1))[ce + 1];
            #pragma unroll
            for (int mt = 0; mt < 2; mt++) {
                #pragma unroll
                for (int rr = 0; rr < 2; rr++) {
                    const int r = m0 + mt * 16 + g + rr * 8;
                    float ve = fmaxf(c[mt][nt][rr * 2] + be, 0.f);
                    float vo = fmaxf(c[mt][nt][rr * 2 + 1] + bo, 0.f);
                    uint32_t lo;
                    uint32_t hi = pack_hi2(ve, vo, lo);
                    *(uint32_t*)(smem + SM_AHI + r * PITCHB + ce * 2) = hi;
                    *(uint32_t*)(smem + SM_ALO + r * PITCHB + ce * 2) = lo;
                }
            }
        }
        __syncthreads();

        // ---- GEMM2 ----
        mma_3pass(smem, SM_B2HI, SM_B2LO, m0, n0, g, t, c);

        // epilogue2: bias2+relu -> fp32 out + stats
        #pragma unroll
        for (int nt = 0; nt < 8; nt++) {
            const int ce = n0 + nt * 8 + 2 * t;
            const float be = ((const float*)(smem + SM_BS2))[ce];
            const float bo = ((const float*)(smem + SM_BS2))[ce + 1];
            float se = 0.f, so = 0.f, qe = 0.f, qo = 0.f;
            #pragma unroll
            for (int mt = 0; mt < 2; mt++) {
                #pragma unroll
                for (int rr = 0; rr < 2; rr++) {
                    const int gr = row0 + m0 + mt * 16 + g + rr * 8;
                    float ve = fmaxf(c[mt][nt][rr * 2] + be, 0.f);
                    float vo = fmaxf(c[mt][nt][rr * 2 + 1] + bo, 0.f);
                    if (gr >= nrows) { ve = 0.f; vo = 0.f; }
                    se += ve; so += vo;
                    qe += ve * ve; qo += vo * vo;
                    if (gr < nrows)
                        *(float2*)(outh + (size_t)gr * DIM + ce) = make_float2(ve, vo);
                }
            }
            #pragma unroll
            for (int o = 4; o < 32; o <<= 1) {
                se += __shfl_xor_sync(~0u, se, o);
                so += __shfl_xor_sync(~0u, so, o);
                qe += __shfl_xor_sync(~0u, qe, o);
                qo += __shfl_xor_sync(~0u, qo, o);
            }
            if (g == 0) {
                float* ps = (float*)(smem + SM_SUM) + wid * 128;
                float* pq = (float*)(smem + SM_SQ) + wid * 128;
                ps[ce] = se; ps[ce + 1] = so;
                pq[ce] = qe; pq[ce + 1] = qo;
            }
        }
        __syncthreads();

        if (tid < 128) {
            const float* ps = (const float*)(smem + SM_SUM);
            float s = 0.f;
            #pragma unroll
            for (int w = 0; w < 8; w++) s += ps[w * 128 + tid];
            atomicAdd(&g_sum[tid], s);
        } else {
            const float* pq = (const float*)(smem + SM_SQ);
            const int f = tid - 128;
            float s = 0.f;
            #pragma unroll
            for (int w = 0; w < 8; w++) s += pq[w * 128 + f];
            atomicAdd(&g_sumsq[f], s);
        }
        __syncthreads();
    }
}

// ---------------- normalize + z_cat slice + graph add-pool (float4) -----------
#define NP_CH 128
__global__ void k_norm_pool(const float* __restrict__ h,
                            const int* __restrict__ batch,
                            const float* __restrict__ gamma,
                            const float* __restrict__ beta,
                            float* __restrict__ zout,
                            float* __restrict__ gout) {
    __shared__ float s_sc[DIM], s_sh[DIM];
    if (threadIdx.x < DIM) {
        int f = threadIdx.x;
        float mean = g_sum[f] * (1.0f / NNODES);
        float var = g_sumsq[f] * (1.0f / NNODES) - mean * mean;
        float inv = rsqrtf(var + BN_EPS);
        float sc = gamma[f] * inv;
        s_sc[f] = sc;
        s_sh[f] = beta[f] - mean * sc;
    }
    __syncthreads();

    const int f4 = (threadIdx.x & 31) * 4;
    const int ln = threadIdx.x >> 5;
    const int r0 = blockIdx.x * NP_CH;
    const int rend = min(r0 + NP_CH, NNODES);
    const float4 sc = *(const float4*)(s_sc + f4);
    const float4 sh = *(const float4*)(s_sh + f4);
    float4 acc = make_float4(0.f, 0.f, 0.f, 0.f);
    int cur = -1;
    for (int r = r0 + ln; r < rend; r += 8) {
        float4 x = *(const float4*)(h + (size_t)r * DIM + f4);
        float4 v;
        v.x = fmaf(x.x, sc.x, sh.x);
        v.y = fmaf(x.y, sc.y, sh.y);
        v.z = fmaf(x.z, sc.z, sh.z);
        v.w = fmaf(x.w, sc.w, sh.w);
        *(float4*)(zout + (size_t)r * (NLAYERS * DIM) + f4) = v;
        int b = batch[r];
        if (b != cur) {
            if (cur >= 0) {
                float* p = gout + (size_t)cur * (NLAYERS * DIM) + f4;
                atomicAdd(p, acc.x); atomicAdd(p + 1, acc.y);
                atomicAdd(p + 2, acc.z); atomicAdd(p + 3, acc.w);
            }
            cur = b;
            acc = v;
        } else {
            acc.x += v.x; acc.y += v.y; acc.z += v.z; acc.w += v.w;
        }
    }
    if (cur >= 0) {
        float* p = gout + (size_t)cur * (NLAYERS * DIM) + f4;
        atomicAdd(p, acc.x); atomicAdd(p + 1, acc.y);
        atomicAdd(p + 2, acc.z); atomicAdd(p + 3, acc.w);
    }
}

// ---------------- launch -------------------------------------------------------
extern "C" void kernel_launch(void* const* d_in, const int* in_sizes, int n_in,
                              void* d_out, int out_size) {
    const float* x     = (const float*)d_in[0];
    const int*   ei    = (const int*)d_in[1];
    const int*   batch = (const int*)d_in[2];
    const float* W1    = (const float*)d_in[3];
    const float* b1    = (const float*)d_in[4];
    const float* W2    = (const float*)d_in[5];
    const float* b2    = (const float*)d_in[6];
    const float* gamma = (const float*)d_in[7];
    const float* beta  = (const float*)d_in[8];

    float* z_cat = (float*)d_out;
    float* g_cat = z_cat + (size_t)NNODES * NLAYERS * DIM;

    cudaFuncSetAttribute(k_mlp, cudaFuncAttributeMaxDynamicSharedMemorySize, SMEM_TOT);

    float* hbuf;  cudaGetSymbolAddress((void**)&hbuf, g_h);
    __nv_bfloat16 *ahi, *alo, *bshi, *bslo;
    cudaGetSymbolAddress((void**)&ahi, g_a_hi);
    cudaGetSymbolAddress((void**)&alo, g_a_lo);
    cudaGetSymbolAddress((void**)&bshi, g_bs_hi);
    cudaGetSymbolAddress((void**)&bslo, g_bs_lo);

    // CSR build + W images (+ pad-tail zeroing in k_zero_cnt)
    k_zero_cnt<<<128, 512>>>(g_cat);
    k_hist<<<(NEDGES / 4 + 511) / 512, 512>>>(ei);
    k_chunksum<<<NCHUNK, 1024>>>();
    k_scanchunks<<<1, 128>>>();
    k_scanwrite<<<NCHUNK, 1024>>>();
    k_fill<<<(NEDGES / 4 + 511) / 512, 512>>>(ei);
    k_wconv<<<6, 256>>>(W1, W2);

    const int np_grid  = (NNODES + NP_CH - 1) / NP_CH;
    const int agg_grid = (NNODES * 32 + 255) / 256;

    for (int l = 0; l < NLAYERS; l++) {
        const float* zin = (l == 0) ? x : (z_cat + (size_t)(l - 1) * DIM);
        const int pin = (l == 0) ? DIM : (NLAYERS * DIM);

        k_aggregate<<<agg_grid, 256>>>(zin, pin);
        k_mlp<<<NSMS, 256, SMEM_TOT>>>(
            ahi, alo,
            bshi + (size_t)(l * 2) * DIM * DIM, bslo + (size_t)(l * 2) * DIM * DIM,
            bshi + (size_t)(l * 2 + 1) * DIM * DIM, bslo + (size_t)(l * 2 + 1) * DIM * DIM,
            b1 + (size_t)l * DIM, b2 + (size_t)l * DIM, hbuf, NNODES);
        k_norm_pool<<<np_grid, 256>>>(hbuf, batch,
                                      gamma + (size_t)l * DIM, beta + (size_t)l * DIM,
                                      z_cat + (size_t)l * DIM,
                                      g_cat + (size_t)l * DIM);
    }
}